// round 14
// baseline (speedup 1.0000x reference)
#include <cuda_runtime.h>
#include <cstdint>

#define N_NODES_MAX 50000
#define DEG_CAP 64   // power of 2 -> shift addressing; max Poisson(16) degree ~40
#define D4 16        // 64 floats = 16 float4 per node row

__device__ int g_cnt[N_NODES_MAX];                // per-dst degree counters
__device__ int g_bucket[N_NODES_MAX * DEG_CAP];   // src ids per dst (12.8 MB)

// Inline dtype detect: interpret first 8 putative int64 entries; true int64
// node ids (< 50000) have zero high words. Random int32 ids make them nonzero.
__device__ __forceinline__ int detect_is32(const unsigned int* __restrict__ w) {
    int is32 = 0;
#pragma unroll
    for (int i = 0; i < 8; i++) is32 |= (w[2 * i + 1] != 0u);
    return is32;
}

__device__ __forceinline__ void bucket_put(int d, int s) {
    int slot = atomicAdd(&g_cnt[d], 1);
    if (slot < DEG_CAP)                    // unreachable guard for this workload;
        g_bucket[d * DEG_CAP + slot] = s;  // protects memory regardless
}

// Vectorized fill: 4 edges per thread (int4 index loads on the int32 path).
__global__ void fill_buckets_kernel(const void* __restrict__ edge_index, int n_edges) {
    int t = blockIdx.x * blockDim.x + threadIdx.x;
    int e0 = t * 4;
    if (e0 >= n_edges) return;
    int is32 = detect_is32((const unsigned int*)edge_index);

    if (is32) {
        const int* ei = (const int*)edge_index;
        if (e0 + 4 <= n_edges && ((e0 & 3) == 0)) {
            int4 s4 = *reinterpret_cast<const int4*>(ei + e0);
            int4 d4 = *reinterpret_cast<const int4*>(ei + n_edges + e0);
            bucket_put(d4.x, s4.x);
            bucket_put(d4.y, s4.y);
            bucket_put(d4.z, s4.z);
            bucket_put(d4.w, s4.w);
        } else {
            for (int e = e0; e < n_edges && e < e0 + 4; e++)
                bucket_put(ei[n_edges + e], ei[e]);
        }
    } else {
        const long long* ei = (const long long*)edge_index;
        for (int e = e0; e < n_edges && e < e0 + 4; e++)
            bucket_put((int)ei[n_edges + e], (int)ei[e]);
    }
}

// EXACT R8/R10 hot kernel — SEALED. Any prologue instruction (even one
// predicated STG) breaks the front-batched LDG MLP and costs ~2x (R9, R11).
__global__ void reduce_kernel(const float4* __restrict__ x_sum,
                              const float4* __restrict__ x_prod,
                              float4* __restrict__ out_sum,
                              float4* __restrict__ out_prod,
                              int n_nodes) {
    int gid = blockIdx.x * blockDim.x + threadIdx.x;
    int d = gid >> 4;
    if (d >= n_nodes) return;
    int c = gid & 15;

    int n = g_cnt[d];
    if (n > DEG_CAP) n = DEG_CAP;
    const int* bkt = &g_bucket[d * DEG_CAP];

    float4 as = make_float4(0.f, 0.f, 0.f, 0.f);
    float4 ap = make_float4(1.f, 1.f, 1.f, 1.f);

    int i = 0;
    // Unrolled x4: one int4 bucket load -> 8 independent float4 gathers in flight.
    for (; i + 4 <= n; i += 4) {
        int4 s4 = *reinterpret_cast<const int4*>(&bkt[i]);   // 16B-aligned
        float4 ms0 = __ldg(&x_sum [s4.x * D4 + c]);
        float4 ms1 = __ldg(&x_sum [s4.y * D4 + c]);
        float4 ms2 = __ldg(&x_sum [s4.z * D4 + c]);
        float4 ms3 = __ldg(&x_sum [s4.w * D4 + c]);
        float4 mp0 = __ldg(&x_prod[s4.x * D4 + c]);
        float4 mp1 = __ldg(&x_prod[s4.y * D4 + c]);
        float4 mp2 = __ldg(&x_prod[s4.z * D4 + c]);
        float4 mp3 = __ldg(&x_prod[s4.w * D4 + c]);

        as.x += ms0.x + ms1.x + ms2.x + ms3.x;
        as.y += ms0.y + ms1.y + ms2.y + ms3.y;
        as.z += ms0.z + ms1.z + ms2.z + ms3.z;
        as.w += ms0.w + ms1.w + ms2.w + ms3.w;

        ap.x *= mp0.x * mp1.x * mp2.x * mp3.x;
        ap.y *= mp0.y * mp1.y * mp2.y * mp3.y;
        ap.z *= mp0.z * mp1.z * mp2.z * mp3.z;
        ap.w *= mp0.w * mp1.w * mp2.w * mp3.w;
    }
    for (; i < n; i++) {
        int s = bkt[i];
        float4 ms = __ldg(&x_sum [s * D4 + c]);
        float4 mp = __ldg(&x_prod[s * D4 + c]);
        as.x += ms.x; as.y += ms.y; as.z += ms.z; as.w += ms.w;
        ap.x *= mp.x; ap.y *= mp.y; ap.z *= mp.z; ap.w *= mp.w;
    }

    out_sum [d * D4 + c] = as;
    out_prod[d * D4 + c] = ap;
}

extern "C" void kernel_launch(void* const* d_in, const int* in_sizes, int n_in,
                              void* d_out, int out_size) {
    const float4* x_sum  = (const float4*)d_in[0];
    const float4* x_prod = (const float4*)d_in[1];
    const void*   ei     = d_in[2];

    const int n_nodes = in_sizes[0] / 64;        // 50000
    const int n_edges = in_sizes[2] / 2;         // 800000
    const int nd      = n_nodes * 64;

    float4* out_sum  = (float4*)d_out;
    float4* out_prod = (float4*)((float*)d_out + nd);

    // 1) zero counters via async memset (graph memset node; no allocation)
    void* cnt_ptr = nullptr;
    cudaGetSymbolAddress(&cnt_ptr, g_cnt);
    cudaMemsetAsync(cnt_ptr, 0, n_nodes * sizeof(int), 0);

    // 2) bucket edges by destination, 4 edges per thread
    {
        int n_threads = (n_edges + 3) / 4;
        fill_buckets_kernel<<<(n_threads + 255) / 256, 256>>>(ei, n_edges);
    }

    // 3) per-destination register reduction, plain stores (no atomics)
    {
        int total = n_nodes * 16;
        reduce_kernel<<<(total + 255) / 256, 256>>>(x_sum, x_prod,
                                                    out_sum, out_prod, n_nodes);
    }
}

// round 15
// speedup vs baseline: 1.0471x; 1.0471x over previous
#include <cuda_runtime.h>
#include <cstdint>

#define N_NODES_MAX 50000
#define DEG_CAP 64   // power of 2 -> shift addressing; max Poisson(16) degree ~40
#define D4 16        // 64 floats = 16 float4 per node row

__device__ int g_cnt[N_NODES_MAX];                // per-dst degree counters (self-cleaning)
__device__ int g_bucket[N_NODES_MAX * DEG_CAP];   // src ids per dst (12.8 MB)

// Inline dtype detect: interpret first 8 putative int64 entries; true int64
// node ids (< 50000) have zero high words. Random int32 ids make them nonzero.
__device__ __forceinline__ int detect_is32(const unsigned int* __restrict__ w) {
    int is32 = 0;
#pragma unroll
    for (int i = 0; i < 8; i++) is32 |= (w[2 * i + 1] != 0u);
    return is32;
}

__global__ void fill_buckets_kernel(const void* __restrict__ edge_index, int n_edges) {
    int e = blockIdx.x * blockDim.x + threadIdx.x;
    if (e >= n_edges) return;
    int is32 = detect_is32((const unsigned int*)edge_index);
    int s, d;
    if (is32) {
        const int* ei = (const int*)edge_index;
        s = ei[e];
        d = ei[n_edges + e];
    } else {
        const long long* ei = (const long long*)edge_index;
        s = (int)ei[e];
        d = (int)ei[n_edges + e];
    }
    int slot = atomicAdd(&g_cnt[d], 1);
    if (slot < DEG_CAP)                    // unreachable guard for this workload;
        g_bucket[d * DEG_CAP + slot] = s;  // protects memory regardless
}

// R8/R10 hot kernel, SEALED body. One change vs R10: counter reset moved to the
// EPILOGUE (after loop + output stores). R11 proved a PROLOGUE reset breaks the
// front-batched LDG MLP (~2x); an end-of-program store cannot join that batch.
__global__ void reduce_kernel(const float4* __restrict__ x_sum,
                              const float4* __restrict__ x_prod,
                              float4* __restrict__ out_sum,
                              float4* __restrict__ out_prod,
                              int n_nodes) {
    int gid = blockIdx.x * blockDim.x + threadIdx.x;
    int d = gid >> 4;
    if (d >= n_nodes) return;
    int c = gid & 15;

    int n = g_cnt[d];
    if (n > DEG_CAP) n = DEG_CAP;
    const int* bkt = &g_bucket[d * DEG_CAP];

    float4 as = make_float4(0.f, 0.f, 0.f, 0.f);
    float4 ap = make_float4(1.f, 1.f, 1.f, 1.f);

    int i = 0;
    // Unrolled x4: one int4 bucket load -> 8 independent float4 gathers in flight.
    for (; i + 4 <= n; i += 4) {
        int4 s4 = *reinterpret_cast<const int4*>(&bkt[i]);   // 16B-aligned
        float4 ms0 = __ldg(&x_sum [s4.x * D4 + c]);
        float4 ms1 = __ldg(&x_sum [s4.y * D4 + c]);
        float4 ms2 = __ldg(&x_sum [s4.z * D4 + c]);
        float4 ms3 = __ldg(&x_sum [s4.w * D4 + c]);
        float4 mp0 = __ldg(&x_prod[s4.x * D4 + c]);
        float4 mp1 = __ldg(&x_prod[s4.y * D4 + c]);
        float4 mp2 = __ldg(&x_prod[s4.z * D4 + c]);
        float4 mp3 = __ldg(&x_prod[s4.w * D4 + c]);

        as.x += ms0.x + ms1.x + ms2.x + ms3.x;
        as.y += ms0.y + ms1.y + ms2.y + ms3.y;
        as.z += ms0.z + ms1.z + ms2.z + ms3.z;
        as.w += ms0.w + ms1.w + ms2.w + ms3.w;

        ap.x *= mp0.x * mp1.x * mp2.x * mp3.x;
        ap.y *= mp0.y * mp1.y * mp2.y * mp3.y;
        ap.z *= mp0.z * mp1.z * mp2.z * mp3.z;
        ap.w *= mp0.w * mp1.w * mp2.w * mp3.w;
    }
    for (; i < n; i++) {
        int s = bkt[i];
        float4 ms = __ldg(&x_sum [s * D4 + c]);
        float4 mp = __ldg(&x_prod[s * D4 + c]);
        as.x += ms.x; as.y += ms.y; as.z += ms.z; as.w += ms.w;
        ap.x *= mp.x; ap.y *= mp.y; ap.z *= mp.z; ap.w *= mp.w;
    }

    out_sum [d * D4 + c] = as;
    out_prod[d * D4 + c] = ap;

    if (c == 0) g_cnt[d] = 0;   // epilogue self-clean (replaces memset node)
}

extern "C" void kernel_launch(void* const* d_in, const int* in_sizes, int n_in,
                              void* d_out, int out_size) {
    const float4* x_sum  = (const float4*)d_in[0];
    const float4* x_prod = (const float4*)d_in[1];
    const void*   ei     = d_in[2];

    const int n_nodes = in_sizes[0] / 64;        // 50000
    const int n_edges = in_sizes[2] / 2;         // 800000
    const int nd      = n_nodes * 64;

    float4* out_sum  = (float4*)d_out;
    float4* out_prod = (float4*)((float*)d_out + nd);

    // 1) bucket edges by destination (counters zero: static init on first call,
    //    epilogue-cleaned by reduce_kernel every call)
    fill_buckets_kernel<<<(n_edges + 255) / 256, 256>>>(ei, n_edges);

    // 2) per-destination register reduction, plain stores; epilogue resets counters
    {
        int total = n_nodes * 16;
        reduce_kernel<<<(total + 255) / 256, 256>>>(x_sum, x_prod,
                                                    out_sum, out_prod, n_nodes);
    }
}

// round 16
// speedup vs baseline: 1.0588x; 1.0112x over previous
#include <cuda_runtime.h>
#include <cstdint>

#define N_NODES_MAX 50000
#define DEG_CAP 64   // power of 2 -> shift addressing; max Poisson(16) degree ~40
#define D4 16        // 64 floats = 16 float4 per node row

__device__ int g_cnt[N_NODES_MAX];                // per-dst degree counters (self-cleaning)
__device__ int g_bucket[N_NODES_MAX * DEG_CAP];   // src ids per dst (12.8 MB)

// Inline dtype detect: interpret first 8 putative int64 entries; true int64
// node ids (< 50000) have zero high words. Random int32 ids make them nonzero.
__device__ __forceinline__ int detect_is32(const unsigned int* __restrict__ w) {
    int is32 = 0;
#pragma unroll
    for (int i = 0; i < 8; i++) is32 |= (w[2 * i + 1] != 0u);
    return is32;
}

__global__ void __launch_bounds__(512)
fill_buckets_kernel(const void* __restrict__ edge_index, int n_edges) {
    int e = blockIdx.x * blockDim.x + threadIdx.x;
    if (e >= n_edges) return;
    int is32 = detect_is32((const unsigned int*)edge_index);
    int s, d;
    if (is32) {
        const int* ei = (const int*)edge_index;
        s = ei[e];
        d = ei[n_edges + e];
    } else {
        const long long* ei = (const long long*)edge_index;
        s = (int)ei[e];
        d = (int)ei[n_edges + e];
    }
    int slot = atomicAdd(&g_cnt[d], 1);
    if (slot < DEG_CAP)                    // unreachable guard for this workload;
        g_bucket[d * DEG_CAP + slot] = s;  // protects memory regardless
}

// SEALED hot kernel (R8/R10 body + epilogue counter reset, proven R14).
// Prologue must stay byte-identical: any instruction between the counter LDG
// and the gather batch costs ~2x (R9, R11). Epilogue additions are free.
__global__ void reduce_kernel(const float4* __restrict__ x_sum,
                              const float4* __restrict__ x_prod,
                              float4* __restrict__ out_sum,
                              float4* __restrict__ out_prod,
                              int n_nodes) {
    int gid = blockIdx.x * blockDim.x + threadIdx.x;
    int d = gid >> 4;
    if (d >= n_nodes) return;
    int c = gid & 15;

    int n = g_cnt[d];
    if (n > DEG_CAP) n = DEG_CAP;
    const int* bkt = &g_bucket[d * DEG_CAP];

    float4 as = make_float4(0.f, 0.f, 0.f, 0.f);
    float4 ap = make_float4(1.f, 1.f, 1.f, 1.f);

    int i = 0;
    // Unrolled x4: one int4 bucket load -> 8 independent float4 gathers in flight.
    for (; i + 4 <= n; i += 4) {
        int4 s4 = *reinterpret_cast<const int4*>(&bkt[i]);   // 16B-aligned
        float4 ms0 = __ldg(&x_sum [s4.x * D4 + c]);
        float4 ms1 = __ldg(&x_sum [s4.y * D4 + c]);
        float4 ms2 = __ldg(&x_sum [s4.z * D4 + c]);
        float4 ms3 = __ldg(&x_sum [s4.w * D4 + c]);
        float4 mp0 = __ldg(&x_prod[s4.x * D4 + c]);
        float4 mp1 = __ldg(&x_prod[s4.y * D4 + c]);
        float4 mp2 = __ldg(&x_prod[s4.z * D4 + c]);
        float4 mp3 = __ldg(&x_prod[s4.w * D4 + c]);

        as.x += ms0.x + ms1.x + ms2.x + ms3.x;
        as.y += ms0.y + ms1.y + ms2.y + ms3.y;
        as.z += ms0.z + ms1.z + ms2.z + ms3.z;
        as.w += ms0.w + ms1.w + ms2.w + ms3.w;

        ap.x *= mp0.x * mp1.x * mp2.x * mp3.x;
        ap.y *= mp0.y * mp1.y * mp2.y * mp3.y;
        ap.z *= mp0.z * mp1.z * mp2.z * mp3.z;
        ap.w *= mp0.w * mp1.w * mp2.w * mp3.w;
    }
    for (; i < n; i++) {
        int s = bkt[i];
        float4 ms = __ldg(&x_sum [s * D4 + c]);
        float4 mp = __ldg(&x_prod[s * D4 + c]);
        as.x += ms.x; as.y += ms.y; as.z += ms.z; as.w += ms.w;
        ap.x *= mp.x; ap.y *= mp.y; ap.z *= mp.z; ap.w *= mp.w;
    }

    out_sum [d * D4 + c] = as;
    out_prod[d * D4 + c] = ap;

    if (c == 0) g_cnt[d] = 0;   // epilogue self-clean (proven free, R14)
}

extern "C" void kernel_launch(void* const* d_in, const int* in_sizes, int n_in,
                              void* d_out, int out_size) {
    const float4* x_sum  = (const float4*)d_in[0];
    const float4* x_prod = (const float4*)d_in[1];
    const void*   ei     = d_in[2];

    const int n_nodes = in_sizes[0] / 64;        // 50000
    const int n_edges = in_sizes[2] / 2;         // 800000
    const int nd      = n_nodes * 64;

    float4* out_sum  = (float4*)d_out;
    float4* out_prod = (float4*)((float*)d_out + nd);

    // 1) bucket edges by destination (counters zero: static init on first call,
    //    epilogue-cleaned by reduce_kernel every call)
    fill_buckets_kernel<<<(n_edges + 511) / 512, 512>>>(ei, n_edges);

    // 2) reduce, launched with a PDL edge: launch setup overlaps fill's tail.
    //    Fill has no explicit trigger -> implicit trigger at full completion
    //    (memory flushed), so reduce needs no griddepcontrol in its body and
    //    the sealed prologue stays untouched.
    {
        int total = n_nodes * 16;
        int blocks = (total + 255) / 256;

        cudaLaunchAttribute attrs[1];
        attrs[0].id = cudaLaunchAttributeProgrammaticStreamSerialization;
        attrs[0].val.programmaticStreamSerializationAllowed = 1;

        cudaLaunchConfig_t cfg = {};
        cfg.gridDim  = dim3(blocks, 1, 1);
        cfg.blockDim = dim3(256, 1, 1);
        cfg.dynamicSmemBytes = 0;
        cfg.stream = 0;
        cfg.attrs = attrs;
        cfg.numAttrs = 1;

        cudaLaunchKernelEx(&cfg, reduce_kernel, x_sum, x_prod,
                           out_sum, out_prod, n_nodes);
    }
}